// round 8
// baseline (speedup 1.0000x reference)
#include <cuda_runtime.h>

// SWT db4, 3 levels, wrap. x:(64,32,4096) f32 -> out:(64,32,4096,4) = [a3,d3,d2,d1].
// out[t] = sum_j f[j] * in[(t + (4-j)*dil) mod 4096], dil = 1,2,4.
//
// Consecutive-4-elements-per-thread + SMEM wrap halos -> all tap windows are
// contiguous 16B-aligned runs read with LDS.128 (conflict-free). SMEM read
// traffic 128 B/elem -> 64 B/elem.

#define SWT_T    4096
#define SWT_NT   512
#define SWT_G    1024            // float4 granules per row
#define HALO_F4L 3               // 12 floats left halo
#define HALO_F4R 4               // 16 floats right halo
#define SLEN4    (HALO_F4L + SWT_G + HALO_F4R)   // 1031 float4 = 16496 B
#define CORE4    HALO_F4L        // float4 index of t=0

__global__ __launch_bounds__(SWT_NT, 2)
void swt_db4_l3_kernel(const float* __restrict__ x,
                       const float* __restrict__ dec_lo,
                       const float* __restrict__ dec_hi,
                       float4* __restrict__ out)
{
    __shared__ float4 s_a[SLEN4];   // x, later lo2
    __shared__ float4 s_b[SLEN4];   // lo1

    const int row = blockIdx.x;
    const int tid = threadIdx.x;

    float flo[8], fhi[8];
#pragma unroll
    for (int j = 0; j < 8; ++j) {
        flo[j] = __ldg(&dec_lo[j]);
        fhi[j] = __ldg(&dec_hi[j]);
    }

    // ---- Load x row (+ wrap halo mirrors) ----
    const float4* xr4 = reinterpret_cast<const float4*>(x + (size_t)row * SWT_T);
#pragma unroll
    for (int s = 0; s < 2; ++s) {
        const int g = tid + s * SWT_NT;          // 0..1023
        float4 v = xr4[g];
        s_a[CORE4 + g] = v;
        if (g < 2)          s_a[CORE4 + SWT_G + g] = v;   // right halo: x[0..8)
        if (g == SWT_G - 1) s_a[CORE4 - 1] = v;           // left halo: x[4092..4096)
    }
    __syncthreads();

    float d1[2][4], d2[2][4];

    // ---- Pass 1 (dil=1): lo1 -> s_b (+halo), d1 -> regs. Window [t0-4,t0+8). ----
#pragma unroll
    for (int s = 0; s < 2; ++s) {
        const int g = tid + s * SWT_NT;          // t0 = 4g
        float lo1[4] = {0.f, 0.f, 0.f, 0.f};
        float hi1[4] = {0.f, 0.f, 0.f, 0.f};
#pragma unroll
        for (int i = 0; i < 3; ++i) {
            const float4 w = s_a[g + 2 + i];     // floats t0-4+4i .. +3
            const float wv[4] = {w.x, w.y, w.z, w.w};
#pragma unroll
            for (int p = 0; p < 4; ++p) {
                const int o = 4 * i - 4 + p;     // offset from t0
#pragma unroll
                for (int c = 0; c < 4; ++c) {
                    const int j = 4 - o + c;     // o = c + (4-j)
                    if (j >= 0 && j <= 7) {
                        lo1[c] = fmaf(flo[j], wv[p], lo1[c]);
                        hi1[c] = fmaf(fhi[j], wv[p], hi1[c]);
                    }
                }
            }
        }
        d1[s][0] = hi1[0]; d1[s][1] = hi1[1]; d1[s][2] = hi1[2]; d1[s][3] = hi1[3];
        const float4 v = make_float4(lo1[0], lo1[1], lo1[2], lo1[3]);
        s_b[CORE4 + g] = v;
        if (g < 2)          s_b[CORE4 + SWT_G + g] = v;          // right halo 8
        if (g >= SWT_G - 2) s_b[CORE4 - 2 + (g - (SWT_G - 2))] = v;  // left halo 8
    }
    __syncthreads();

    // ---- Pass 2 (dil=2): lo2 -> s_a (+halo), d2 -> regs. Window [t0-8,t0+12). ----
#pragma unroll
    for (int s = 0; s < 2; ++s) {
        const int g = tid + s * SWT_NT;
        float lo2[4] = {0.f, 0.f, 0.f, 0.f};
        float hi2[4] = {0.f, 0.f, 0.f, 0.f};
#pragma unroll
        for (int i = 0; i < 5; ++i) {
            const float4 w = s_b[g + 1 + i];     // floats t0-8+4i .. +3
            const float wv[4] = {w.x, w.y, w.z, w.w};
#pragma unroll
            for (int p = 0; p < 4; ++p) {
                const int o = 4 * i - 8 + p;
#pragma unroll
                for (int c = (o & 1); c < 4; c += 2) {   // o-c must be even
                    const int j = 4 - (o - c) / 2;       // o = c + 2(4-j)
                    if (j >= 0 && j <= 7) {
                        lo2[c] = fmaf(flo[j], wv[p], lo2[c]);
                        hi2[c] = fmaf(fhi[j], wv[p], hi2[c]);
                    }
                }
            }
        }
        d2[s][0] = hi2[0]; d2[s][1] = hi2[1]; d2[s][2] = hi2[2]; d2[s][3] = hi2[3];
        const float4 v = make_float4(lo2[0], lo2[1], lo2[2], lo2[3]);
        s_a[CORE4 + g] = v;
        if (g < 4)          s_a[CORE4 + SWT_G + g] = v;          // right halo 16
        if (g >= SWT_G - 3) s_a[(g - (SWT_G - 3))] = v;          // left halo 12
    }
    __syncthreads();

    // ---- Pass 3 (dil=4): a3/d3 from s_a (lo2). Window [t0-12,t0+20). Write out. ----
    float4* out_row = out + (size_t)row * SWT_T;
#pragma unroll
    for (int s = 0; s < 2; ++s) {
        const int g = tid + s * SWT_NT;
        const int t0 = 4 * g;
        float a3[4] = {0.f, 0.f, 0.f, 0.f};
        float d3[4] = {0.f, 0.f, 0.f, 0.f};
#pragma unroll
        for (int i = 0; i < 8; ++i) {
            const float4 w = s_a[g + i];         // floats t0-12+4i .. +3
            const float wv[4] = {w.x, w.y, w.z, w.w};
            const float cl = flo[7 - i];         // 4(i-3) = (4-j)*4  ->  j = 7-i
            const float ch = fhi[7 - i];
#pragma unroll
            for (int c = 0; c < 4; ++c) {
                a3[c] = fmaf(cl, wv[c], a3[c]);
                d3[c] = fmaf(ch, wv[c], d3[c]);
            }
        }
#pragma unroll
        for (int c = 0; c < 4; ++c)
            out_row[t0 + c] = make_float4(a3[c], d3[c], d2[s][c], d1[s][c]);
    }
}

extern "C" void kernel_launch(void* const* d_in, const int* in_sizes, int n_in,
                              void* d_out, int out_size)
{
    const float* x      = (const float*)d_in[0];
    const float* dec_lo = (const float*)d_in[1];
    const float* dec_hi = (const float*)d_in[2];
    float4* out         = (float4*)d_out;

    const int rows = in_sizes[0] / SWT_T;   // 2048
    swt_db4_l3_kernel<<<rows, SWT_NT>>>(x, dec_lo, dec_hi, out);
}

// round 9
// speedup vs baseline: 1.5520x; 1.5520x over previous
#include <cuda_runtime.h>

// SWT db4, 3 levels, wrap. x:(64,32,4096) f32 -> out:(64,32,4096,4) = [a3,d3,d2,d1].
// out[t] = sum_j f[j] * in[(t + (4-j)*dil) mod 4096], dil = 1,2,4.
//
// R9: hybrid mapping.
//  - Pass1 (dil=1) & Pass2 (dil=2): vectorized (1 float4-granule / thread / sweep),
//    contiguous LDS.128 windows via halos; d1/d2 staged to scalar SMEM via STS.128.
//  - Pass3 (dil=4): scalar strided mapping (vectorization has no reuse at dil=4),
//    lane-contiguous STG.128 output (no wavefront inflation), d1/d2 from staging.

#define SWT_T   4096
#define SWT_G   1024
#define SWT_NT  512

// Buffer A: x (CORE=1, reads granules [g-1,g+3)) then lo2 (CORE=3, scalar reads
// [t-12, t+16]). len = max(1+1024+3, 3+1024+4) = 1031 granules.
#define A_LEN    1031
#define X_CORE   1
#define LO2_CORE 3
// Buffer B: lo1 (CORE=2, reads granules [g-2,g+3)). len = 2+1024+3 = 1029.
#define B_LEN   1029
#define B_CORE  2

#define SMEM_BYTES ((A_LEN + B_LEN) * 16 + 2 * SWT_T * 4)   // 65728

__global__ __launch_bounds__(SWT_NT, 3)
void swt_db4_l3_kernel(const float* __restrict__ x,
                       const float* __restrict__ dec_lo,
                       const float* __restrict__ dec_hi,
                       float4* __restrict__ out)
{
    extern __shared__ unsigned char smem_raw[];
    float4* s_ab = reinterpret_cast<float4*>(smem_raw);       // A: x, later lo2
    float4* s_b  = s_ab + A_LEN;                              // B: lo1
    float*  s_d2 = reinterpret_cast<float*>(s_b + B_LEN);     // [4096] d2
    float*  s_d1 = s_d2 + SWT_T;                              // [4096] d1

    const int row = blockIdx.x;
    const int tid = threadIdx.x;

    float flo[8], fhi[8];
#pragma unroll
    for (int j = 0; j < 8; ++j) {
        flo[j] = __ldg(&dec_lo[j]);
        fhi[j] = __ldg(&dec_hi[j]);
    }

    // ---- Load x row + wrap halos (granules [-1, 1027) around core) ----
    const float4* xr4 = reinterpret_cast<const float4*>(x + (size_t)row * SWT_T);
#pragma unroll
    for (int s = 0; s < 2; ++s) {
        const int g = tid + s * SWT_NT;
        float4 v = xr4[g];
        s_ab[X_CORE + g] = v;
        if (g == SWT_G - 1) s_ab[0] = v;                      // left halo: x[4092..)
        if (g < 3)          s_ab[X_CORE + SWT_G + g] = v;     // right halo: x[0..12)
    }
    __syncthreads();

    // ---- Pass 1 (dil=1): lo1 -> s_b (+halos), d1 -> s_d1. Window [t0-4,t0+8). ----
#pragma unroll
    for (int s = 0; s < 2; ++s) {
        const int g = tid + s * SWT_NT;          // t0 = 4g
        float lo1[4] = {0.f, 0.f, 0.f, 0.f};
        float hi1[4] = {0.f, 0.f, 0.f, 0.f};
#pragma unroll
        for (int i = 0; i < 3; ++i) {
            const float4 w = s_ab[g + i];        // == granule g-1+i of x
            const float wv[4] = {w.x, w.y, w.z, w.w};
#pragma unroll
            for (int p = 0; p < 4; ++p) {
                const int o = 4 * i - 4 + p;
#pragma unroll
                for (int c = 0; c < 4; ++c) {
                    const int j = 4 - o + c;
                    if (j >= 0 && j <= 7) {
                        lo1[c] = fmaf(flo[j], wv[p], lo1[c]);
                        hi1[c] = fmaf(fhi[j], wv[p], hi1[c]);
                    }
                }
            }
        }
        const float4 v = make_float4(lo1[0], lo1[1], lo1[2], lo1[3]);
        s_b[B_CORE + g] = v;
        if (g >= SWT_G - 2) s_b[B_CORE + g - SWT_G] = v;      // left halo (2)
        if (g < 3)          s_b[B_CORE + SWT_G + g] = v;      // right halo (3)
        reinterpret_cast<float4*>(s_d1)[g] =
            make_float4(hi1[0], hi1[1], hi1[2], hi1[3]);
    }
    __syncthreads();

    // ---- Pass 2 (dil=2): lo2 -> s_ab (+halos), d2 -> s_d2. Window [t0-8,t0+12). ----
#pragma unroll
    for (int s = 0; s < 2; ++s) {
        const int g = tid + s * SWT_NT;
        float lo2[4] = {0.f, 0.f, 0.f, 0.f};
        float hi2[4] = {0.f, 0.f, 0.f, 0.f};
#pragma unroll
        for (int i = 0; i < 5; ++i) {
            const float4 w = s_b[g + i];         // == granule g-2+i of lo1
            const float wv[4] = {w.x, w.y, w.z, w.w};
#pragma unroll
            for (int p = 0; p < 4; ++p) {
                const int o = 4 * i - 8 + p;
#pragma unroll
                for (int c = (o & 1); c < 4; c += 2) {
                    const int j = 4 - (o - c) / 2;
                    if (j >= 0 && j <= 7) {
                        lo2[c] = fmaf(flo[j], wv[p], lo2[c]);
                        hi2[c] = fmaf(fhi[j], wv[p], hi2[c]);
                    }
                }
            }
        }
        const float4 v = make_float4(lo2[0], lo2[1], lo2[2], lo2[3]);
        s_ab[LO2_CORE + g] = v;
        if (g >= SWT_G - 3) s_ab[LO2_CORE + g - SWT_G] = v;   // left halo (3)
        if (g < 4)          s_ab[LO2_CORE + SWT_G + g] = v;   // right halo (4)
        reinterpret_cast<float4*>(s_d2)[g] =
            make_float4(hi2[0], hi2[1], hi2[2], hi2[3]);
    }
    __syncthreads();

    // ---- Pass 3 (dil=4), scalar strided: a3/d3 from lo2, merge staged d2/d1,
    //      lane-contiguous STG.128. Taps at t + 4i - 12, i=0..7 (j = 7-i). ----
    const float* lo2f = reinterpret_cast<const float*>(s_ab) + 4 * LO2_CORE;
    float4* out_row = out + (size_t)row * SWT_T;
#pragma unroll
    for (int r = 0; r < 8; ++r) {
        const int t = tid + r * SWT_NT;
        float a3 = 0.f, d3 = 0.f;
#pragma unroll
        for (int i = 0; i < 8; ++i) {
            const float v = lo2f[t + 4 * i - 12];
            a3 = fmaf(flo[7 - i], v, a3);
            d3 = fmaf(fhi[7 - i], v, d3);
        }
        out_row[t] = make_float4(a3, d3, s_d2[t], s_d1[t]);
    }
}

extern "C" void kernel_launch(void* const* d_in, const int* in_sizes, int n_in,
                              void* d_out, int out_size)
{
    const float* x      = (const float*)d_in[0];
    const float* dec_lo = (const float*)d_in[1];
    const float* dec_hi = (const float*)d_in[2];
    float4* out         = (float4*)d_out;

    // Idempotent, host-side, capture-safe: raise dynamic SMEM limit.
    cudaFuncSetAttribute(swt_db4_l3_kernel,
                         cudaFuncAttributeMaxDynamicSharedMemorySize, SMEM_BYTES);

    const int rows = in_sizes[0] / SWT_T;   // 2048
    swt_db4_l3_kernel<<<rows, SWT_NT, SMEM_BYTES>>>(x, dec_lo, dec_hi, out);
}